// round 12
// baseline (speedup 1.0000x reference)
#include <cuda_runtime.h>
#include <math.h>
#include <stdint.h>

#define B_ 8
#define N_ 1024
#define C_ 768
#define H_ 12
#define D_ 64
#define BH_ (B_*H_)

// Scratch (device globals — no allocation allowed)
__device__ float    g_q [BH_*N_*D_];    // fp32 from GEMM; LN rewrites as tf32 bits
__device__ float    g_k [BH_*N_*D_];    // fp32 from GEMM; LN rewrites as tf32 bits
__device__ uint32_t g_v [BH_*N_*D_];    // tf32 bits (GEMM epilogue converts)
__device__ uint32_t g_ao[B_*N_*C_];     // attention output, tf32 bits, [B,N,C]
__device__ uint32_t gx_tf [B_*N_*C_];   // x pre-converted to tf32 bits
__device__ uint32_t gw1_tf[3*C_*C_];    // wqkv pre-converted
__device__ uint32_t gw2_tf[C_*C_];      // wproj pre-converted

// ---------------------------------------------------------------------------
// helpers
// ---------------------------------------------------------------------------
__device__ __forceinline__ uint32_t f2tf(float f) {
    uint32_t u;
    asm("cvt.rna.tf32.f32 %0, %1;" : "=r"(u) : "f"(f));
    return u;
}

__device__ __forceinline__ void mma8(float* c, const uint32_t* a, const uint32_t* b) {
    asm volatile(
        "mma.sync.aligned.m16n8k8.row.col.f32.tf32.tf32.f32 "
        "{%0,%1,%2,%3},{%4,%5,%6,%7},{%8,%9},{%0,%1,%2,%3};"
        : "+f"(c[0]), "+f"(c[1]), "+f"(c[2]), "+f"(c[3])
        : "r"(a[0]), "r"(a[1]), "r"(a[2]), "r"(a[3]), "r"(b[0]), "r"(b[1]));
}

__device__ __forceinline__ uint32_t smem_u32(const void* p) {
    uint32_t a;
    asm("{ .reg .u64 t; cvta.to.shared.u64 t, %1; cvt.u32.u64 %0, t; }"
        : "=r"(a) : "l"(p));
    return a;
}

__device__ __forceinline__ void ldsm4(uint32_t* r, uint32_t addr) {
    asm volatile("ldmatrix.sync.aligned.m8n8.x4.shared.b16 {%0,%1,%2,%3}, [%4];"
        : "=r"(r[0]), "=r"(r[1]), "=r"(r[2]), "=r"(r[3]) : "r"(addr));
}

__device__ __forceinline__ void cpasync16(uint32_t smem_addr, const void* gptr) {
    asm volatile("cp.async.cg.shared.global [%0], [%1], 16;"
        :: "r"(smem_addr), "l"(gptr) : "memory");
}
#define CP_COMMIT() asm volatile("cp.async.commit_group;" ::: "memory")

// ---------------------------------------------------------------------------
// Pre-convert pass: x, wqkv, wproj -> tf32 bit arrays
// ---------------------------------------------------------------------------
#define NXV ((B_*N_*C_)/4)
#define NW1V ((3*C_*C_)/4)
#define NW2V ((C_*C_)/4)
#define NTOTV (NXV + NW1V + NW2V)

__global__ __launch_bounds__(256)
void cvt_kernel(const float4* __restrict__ x, const float4* __restrict__ w1,
                const float4* __restrict__ w2)
{
    const int i = blockIdx.x * blockDim.x + threadIdx.x;
    if (i >= NTOTV) return;
    float4 v; uint4* dst;
    if (i < NXV)            { v = x[i];               dst = (uint4*)gx_tf  + i; }
    else if (i < NXV+NW1V)  { v = w1[i - NXV];        dst = (uint4*)gw1_tf + (i - NXV); }
    else                    { v = w2[i - NXV - NW1V]; dst = (uint4*)gw2_tf + (i - NXV - NW1V); }
    *dst = make_uint4(f2tf(v.x), f2tf(v.y), f2tf(v.z), f2tf(v.w));
}

// ---------------------------------------------------------------------------
// tf32 GEMM on pre-converted inputs (R11 structure, cp.async 3-stage, LDSM).
// MODE 0: q,k scattered fp32; v scattered as tf32 BITS.
// MODE 1: row-major fp32 store to Y.
// ---------------------------------------------------------------------------
#define KPG 36
#define STG_W (128*KPG)

template<int MODE>
__global__ __launch_bounds__(256)
void gemm_tf32(const uint32_t* __restrict__ A, const uint32_t* __restrict__ W,
               float* __restrict__ Y)
{
    extern __shared__ uint32_t smem[];
    uint32_t* As = smem;
    uint32_t* Ws = smem + 3*STG_W;

    const int tid  = threadIdx.x;
    const int warp = tid >> 5, lane = tid & 31;
    const int g    = lane >> 2, tig = lane & 3;
    const int wm   = (warp >> 2) * 64;
    const int wn   = (warp & 3)  * 32;
    const int bm   = blockIdx.y * 128;
    const int bn   = blockIdx.x * 128;
    const int K    = C_;
    const int nk   = K / 32;

    const int lrow = tid >> 1;
    const int lhf  = (tid & 1) * 16;
    const uint32_t sA0 = smem_u32(As) + (uint32_t)((lrow*KPG + lhf) * 4);
    const uint32_t sW0 = smem_u32(Ws) + (uint32_t)((lrow*KPG + lhf) * 4);
    const uint32_t* gA = A + (size_t)(bm + lrow) * K + lhf;
    const uint32_t* gW = W + (size_t)(bn + lrow) * K + lhf;

    const uint32_t a_lane = smem_u32(As)
        + (uint32_t)((((wm + (lane & 15)) * KPG + ((lane >> 4) << 2))) * 4);
    const uint32_t b_lane = smem_u32(Ws)
        + (uint32_t)((((wn + (lane & 7) + ((lane >> 4) << 3)) * KPG
                      + (((lane >> 3) & 1) << 2))) * 4);

    float acc[4][4][4];
    #pragma unroll
    for (int i = 0; i < 4; i++)
        #pragma unroll
        for (int j = 0; j < 4; j++)
            #pragma unroll
            for (int e = 0; e < 4; e++) acc[i][j][e] = 0.f;

    auto issue = [&](int s) {
        const uint32_t so = (uint32_t)((s % 3) * STG_W * 4);
        const uint32_t* ga = gA + s*32;
        const uint32_t* gw = gW + s*32;
        #pragma unroll
        for (int q = 0; q < 4; q++) {
            cpasync16(sA0 + so + q*16, ga + q*4);
            cpasync16(sW0 + so + q*16, gw + q*4);
        }
        CP_COMMIT();
    };

    issue(0);
    if (nk > 1) issue(1);

    for (int i = 0; i < nk; i++) {
        if (i + 1 < nk) asm volatile("cp.async.wait_group 1;" ::: "memory");
        else            asm volatile("cp.async.wait_group 0;" ::: "memory");
        __syncthreads();
        if (i + 2 < nk) issue(i + 2);

        const uint32_t ab = a_lane + (uint32_t)((i % 3) * STG_W * 4);
        const uint32_t bb = b_lane + (uint32_t)((i % 3) * STG_W * 4);
        #pragma unroll
        for (int kk = 0; kk < 4; kk++) {
            const uint32_t kko = kk * 32;
            uint32_t af[4][4];
            #pragma unroll
            for (int mf = 0; mf < 4; mf++)
                ldsm4(af[mf], ab + (uint32_t)(mf*16*KPG*4) + kko);
            uint32_t bf0[4], bf1[4];
            ldsm4(bf0, bb + kko);
            ldsm4(bf1, bb + (uint32_t)(16*KPG*4) + kko);
            #pragma unroll
            for (int mf = 0; mf < 4; mf++) {
                mma8(acc[mf][0], af[mf], &bf0[0]);
                mma8(acc[mf][1], af[mf], &bf0[2]);
                mma8(acc[mf][2], af[mf], &bf1[0]);
                mma8(acc[mf][3], af[mf], &bf1[2]);
            }
        }
    }

    // epilogue
    #pragma unroll
    for (int mf = 0; mf < 4; mf++) {
        #pragma unroll
        for (int rr = 0; rr < 2; rr++) {
            const int m = bm + wm + mf*16 + g + rr*8;
            const int b = m >> 10;
            const int n = m & 1023;
            #pragma unroll
            for (int nf = 0; nf < 4; nf++) {
                const int c = bn + wn + nf*8 + 2*tig;
                const float vx = acc[mf][nf][rr*2 + 0];
                const float vy = acc[mf][nf][rr*2 + 1];
                if (MODE == 1) {
                    float2 v2; v2.x = vx; v2.y = vy;
                    *(float2*)&Y[(size_t)m * C_ + c] = v2;
                } else {
                    const int s = c / C_;
                    const int w = c - s * C_;
                    const int h = w >> 6;
                    const int d = w & 63;
                    const int idx = ((b*H_ + h)*N_ + n)*D_ + d;
                    if (s == 0) {
                        float2 v2; v2.x = vx; v2.y = vy;
                        *(float2*)&g_q[idx] = v2;
                    } else if (s == 1) {
                        float2 v2; v2.x = vx; v2.y = vy;
                        *(float2*)&g_k[idx] = v2;
                    } else {
                        *(uint2*)&g_v[idx] = make_uint2(f2tf(vx), f2tf(vy));
                    }
                }
            }
        }
    }
}

// ---------------------------------------------------------------------------
// Per-head LayerNorm over D=64 (q also *SCALE). Reads fp32, WRITES TF32 BITS.
// ---------------------------------------------------------------------------
__global__ __launch_bounds__(256)
void ln_kernel()
{
    const int warp = (blockIdx.x * blockDim.x + threadIdx.x) >> 5;
    const int lane = threadIdx.x & 31;
    const int nrows = BH_ * N_;
    if (warp >= 2 * nrows) return;

    float* buf  = (warp < nrows) ? g_q : g_k;
    const float scale = (warp < nrows) ? 0.125f : 1.0f;
    const int row = (warp < nrows) ? warp : warp - nrows;

    float2 x = *(float2*)&buf[(size_t)row*64 + lane*2];
    float sum = x.x + x.y;
    #pragma unroll
    for (int o = 16; o > 0; o >>= 1) sum += __shfl_xor_sync(0xffffffffu, sum, o);
    const float mean = sum * (1.0f/64.0f);
    const float dx = x.x - mean, dy = x.y - mean;
    float vs = dx*dx + dy*dy;
    #pragma unroll
    for (int o = 16; o > 0; o >>= 1) vs += __shfl_xor_sync(0xffffffffu, vs, o);
    const float inv = rsqrtf(vs * (1.0f/64.0f) + 1e-5f) * scale;
    *(uint2*)&((uint32_t*)buf)[(size_t)row*64 + lane*2] =
        make_uint2(f2tf(dx * inv), f2tf(dy * inv));
}

// ---------------------------------------------------------------------------
// Flash attention v2: 256 threads, 128 q rows/block, all operands tf32 bits.
// Staging = pure uint4 copies; V transposed via 4x4 register blocks (STS.128,
// conflict-free). Warp w handles q rows [16w, 16w+16).
// ---------------------------------------------------------------------------
#define FPT 68

__global__ __launch_bounds__(256, 2)
void flash_tf32()
{
    extern __shared__ uint32_t fsm[];
    uint32_t* Ks = fsm;                 // [64][FPT]  K tile bits
    uint32_t* Vt = Ks + 64*FPT;         // [64][FPT]  V^T bits (row=d)
    uint32_t* Qs = Vt + 64*FPT;         // [128][FPT] Q bits
    uint32_t* Ps = Qs + 128*FPT;        // [128][FPT] P bits

    const int bh    = blockIdx.y;
    const int qtile = blockIdx.x;       // 0..7 (128 rows each)
    const int b = bh / H_;
    const int h = bh - b * H_;

    const uint32_t* Qb = (const uint32_t*)g_q + (size_t)bh * N_ * D_
                       + (size_t)qtile * 128 * D_;
    const uint32_t* Kb = (const uint32_t*)g_k + (size_t)bh * N_ * D_;
    const uint32_t* Vb = g_v + (size_t)bh * N_ * D_;

    const int tid  = threadIdx.x;
    const int warp = tid >> 5, lane = tid & 31;
    const int g    = lane >> 2, tig = lane & 3;
    const int wband = warp * 16;

    // ldsm lane addresses
    const uint32_t bRowOff = (uint32_t)(((lane & 7) + ((lane >> 4) << 3)) * FPT
                                        + (((lane >> 3) & 1) << 2)) * 4;
    const uint32_t kb_lane = smem_u32(Ks) + bRowOff;
    const uint32_t vb_lane = smem_u32(Vt) + bRowOff;
    const uint32_t aRowOff = (uint32_t)(((wband + (lane & 15)) * FPT
                                        + ((lane >> 4) << 2)) * 4);
    const uint32_t qa_lane = smem_u32(Qs) + aRowOff;
    const uint32_t pa_lane = smem_u32(Ps) + aRowOff;

    // stage Q once (bit copies)
    for (int i = tid; i < 128*16; i += 256) {
        const int r = i >> 4, cv = (i & 15) << 2;
        *(uint4*)&Qs[r*FPT + cv] = *(const uint4*)(Qb + r*64 + cv);
    }

    // V transpose mapping: thread -> 4x4 block (key0, d0)
    const int key0 = (tid & 15) * 4;
    const int d0   = (tid >> 4) * 4;

    float o[8][4];
    #pragma unroll
    for (int nf = 0; nf < 8; nf++)
        #pragma unroll
        for (int e = 0; e < 4; e++) o[nf][e] = 0.f;
    float m0 = -1e30f, m1 = -1e30f, l0 = 0.f, l1 = 0.f;

    __syncthreads();   // Q staged (also covers first K/V stage ordering)

    for (int j = 0; j < 16; j++) {
        __syncthreads();   // prior iter done reading Ks/Vt
        // K tile: straight bit copy
        for (int i = tid; i < 64*16; i += 256) {
            const int r = i >> 4, cv = (i & 15) << 2;
            *(uint4*)&Ks[r*FPT + cv] = *(const uint4*)(Kb + (size_t)j*4096 + r*64 + cv);
        }
        // V tile: 4x4 register transpose, vectorized conflict-free stores
        {
            const uint32_t* vsrc = Vb + (size_t)j*4096 + key0*64 + d0;
            uint4 r0 = *(const uint4*)(vsrc);
            uint4 r1 = *(const uint4*)(vsrc + 64);
            uint4 r2 = *(const uint4*)(vsrc + 128);
            uint4 r3 = *(const uint4*)(vsrc + 192);
            *(uint4*)&Vt[(d0+0)*FPT + key0] = make_uint4(r0.x, r1.x, r2.x, r3.x);
            *(uint4*)&Vt[(d0+1)*FPT + key0] = make_uint4(r0.y, r1.y, r2.y, r3.y);
            *(uint4*)&Vt[(d0+2)*FPT + key0] = make_uint4(r0.z, r1.z, r2.z, r3.z);
            *(uint4*)&Vt[(d0+3)*FPT + key0] = make_uint4(r0.w, r1.w, r2.w, r3.w);
        }
        __syncthreads();

        // S = Q @ K^T   (warp: 16 rows x 64 cols)
        float s[8][4];
        #pragma unroll
        for (int nf = 0; nf < 8; nf++)
            #pragma unroll
            for (int e = 0; e < 4; e++) s[nf][e] = 0.f;

        #pragma unroll
        for (int kf = 0; kf < 8; kf++) {
            uint32_t qaf[4];
            ldsm4(qaf, qa_lane + kf*32);
            uint32_t bfr[4][4];
            #pragma unroll
            for (int nfp = 0; nfp < 4; nfp++)
                ldsm4(bfr[nfp], kb_lane + (uint32_t)((nfp*16*FPT + kf*8) * 4));
            #pragma unroll
            for (int nf = 0; nf < 8; nf++)
                mma8(s[nf], qaf, &bfr[nf >> 1][(nf & 1) * 2]);
        }

        // online softmax (rows r0 = wband+g, r1 = r0+8)
        float mx0 = -1e30f, mx1 = -1e30f;
        #pragma unroll
        for (int nf = 0; nf < 8; nf++) {
            mx0 = fmaxf(mx0, fmaxf(s[nf][0], s[nf][1]));
            mx1 = fmaxf(mx1, fmaxf(s[nf][2], s[nf][3]));
        }
        mx0 = fmaxf(mx0, __shfl_xor_sync(0xffffffffu, mx0, 1));
        mx0 = fmaxf(mx0, __shfl_xor_sync(0xffffffffu, mx0, 2));
        mx1 = fmaxf(mx1, __shfl_xor_sync(0xffffffffu, mx1, 1));
        mx1 = fmaxf(mx1, __shfl_xor_sync(0xffffffffu, mx1, 2));

        const float mn0 = fmaxf(m0, mx0);
        const float mn1 = fmaxf(m1, mx1);
        const float corr0 = __expf(m0 - mn0);
        const float corr1 = __expf(m1 - mn1);
        m0 = mn0; m1 = mn1;

        float rs0 = 0.f, rs1 = 0.f;
        #pragma unroll
        for (int nf = 0; nf < 8; nf++) {
            const float p0 = __expf(s[nf][0] - mn0);
            const float p1 = __expf(s[nf][1] - mn0);
            const float p2 = __expf(s[nf][2] - mn1);
            const float p3 = __expf(s[nf][3] - mn1);
            rs0 += p0 + p1;
            rs1 += p2 + p3;
            *(uint2*)&Ps[(wband + g    )*FPT + nf*8 + 2*tig] =
                make_uint2(f2tf(p0), f2tf(p1));
            *(uint2*)&Ps[(wband + g + 8)*FPT + nf*8 + 2*tig] =
                make_uint2(f2tf(p2), f2tf(p3));
        }
        rs0 += __shfl_xor_sync(0xffffffffu, rs0, 1);
        rs0 += __shfl_xor_sync(0xffffffffu, rs0, 2);
        rs1 += __shfl_xor_sync(0xffffffffu, rs1, 1);
        rs1 += __shfl_xor_sync(0xffffffffu, rs1, 2);
        l0 = l0 * corr0 + rs0;
        l1 = l1 * corr1 + rs1;

        #pragma unroll
        for (int nf = 0; nf < 8; nf++) {
            o[nf][0] *= corr0; o[nf][1] *= corr0;
            o[nf][2] *= corr1; o[nf][3] *= corr1;
        }
        __syncwarp();

        // O += P @ V
        #pragma unroll
        for (int kf = 0; kf < 8; kf++) {
            uint32_t pa[4];
            ldsm4(pa, pa_lane + kf*32);
            uint32_t bv[4][4];
            #pragma unroll
            for (int nfp = 0; nfp < 4; nfp++)
                ldsm4(bv[nfp], vb_lane + (uint32_t)((nfp*16*FPT + kf*8) * 4));
            #pragma unroll
            for (int nf = 0; nf < 8; nf++)
                mma8(o[nf], pa, &bv[nf >> 1][(nf & 1) * 2]);
        }
        __syncwarp();
    }

    // epilogue: O / l -> g_ao as tf32 bits
    const float inv0 = 1.0f / l0;
    const float inv1 = 1.0f / l1;
    const int n0 = qtile*128 + wband + g;
    const int n1 = n0 + 8;
    #pragma unroll
    for (int nf = 0; nf < 8; nf++) {
        const int d = h*64 + nf*8 + 2*tig;
        *(uint2*)&g_ao[((size_t)b*N_ + n0)*C_ + d] =
            make_uint2(f2tf(o[nf][0]*inv0), f2tf(o[nf][1]*inv0));
        *(uint2*)&g_ao[((size_t)b*N_ + n1)*C_ + d] =
            make_uint2(f2tf(o[nf][2]*inv1), f2tf(o[nf][3]*inv1));
    }
}

// ---------------------------------------------------------------------------
extern "C" void kernel_launch(void* const* d_in, const int* in_sizes, int n_in,
                              void* d_out, int out_size)
{
    const float* x     = (const float*)d_in[0];   // [B,N,C]
    const float* wqkv  = (const float*)d_in[1];   // [3C,C]
    const float* wproj = (const float*)d_in[2];   // [C,C]
    float* out = (float*)d_out;                   // [B,N,C]

    uint32_t* d_gx;  cudaGetSymbolAddress((void**)&d_gx,  gx_tf);
    uint32_t* d_gw1; cudaGetSymbolAddress((void**)&d_gw1, gw1_tf);
    uint32_t* d_gw2; cudaGetSymbolAddress((void**)&d_gw2, gw2_tf);
    uint32_t* d_gao; cudaGetSymbolAddress((void**)&d_gao, g_ao);

    const int gsmem = 6 * STG_W * (int)sizeof(uint32_t);   // 110592

    // 0) pre-convert x, wqkv, wproj to tf32 bits
    {
        const int blocks = (NTOTV + 255) / 256;
        cvt_kernel<<<blocks, 256>>>((const float4*)x, (const float4*)wqkv,
                                    (const float4*)wproj);
    }

    // 1) QKV GEMM -> q/k fp32, v tf32 bits
    {
        cudaFuncSetAttribute(gemm_tf32<0>,
                             cudaFuncAttributeMaxDynamicSharedMemorySize, gsmem);
        dim3 grid(3*C_/128, (B_*N_)/128);   // (18, 64)
        gemm_tf32<0><<<grid, 256, gsmem>>>(d_gx, d_gw1, nullptr);
    }

    // 2) LayerNorm on q (*SCALE) and k -> tf32 bits in place
    {
        const int warps = 2 * BH_ * N_;
        const int blocks = (warps * 32 + 255) / 256;
        ln_kernel<<<blocks, 256>>>();
    }

    // 3) Flash attention -> g_ao (tf32 bits)
    {
        const int fsmem = (2*64*FPT + 2*128*FPT) * (int)sizeof(uint32_t);  // 104448
        cudaFuncSetAttribute(flash_tf32,
                             cudaFuncAttributeMaxDynamicSharedMemorySize, fsmem);
        dim3 grid(N_/128, BH_);   // (8, 96)
        flash_tf32<<<grid, 256, fsmem>>>();
    }

    // 4) Output projection (A = g_ao tf32 bits)
    {
        cudaFuncSetAttribute(gemm_tf32<1>,
                             cudaFuncAttributeMaxDynamicSharedMemorySize, gsmem);
        dim3 grid(C_/128, (B_*N_)/128);     // (6, 64)
        gemm_tf32<1><<<grid, 256, gsmem>>>(d_gao, d_gw2, out);
    }
}

// round 13
// speedup vs baseline: 1.1020x; 1.1020x over previous
#include <cuda_runtime.h>
#include <math.h>
#include <stdint.h>

#define B_ 8
#define N_ 1024
#define C_ 768
#define H_ 12
#define D_ 64
#define BH_ (B_*H_)

// Scratch (device globals — no allocation allowed)
__device__ float    g_q [BH_*N_*D_];    // fp32 from GEMM; LN rewrites tf32 bits
__device__ float    g_k [BH_*N_*D_];    // fp32 from GEMM; LN rewrites tf32 bits
__device__ uint32_t g_vt[BH_*D_*N_];    // V^T tf32 bits: [bh][d][n]
__device__ uint32_t g_ao[B_*N_*C_];     // attention output, tf32 bits, [B,N,C]
__device__ uint32_t gx_tf [B_*N_*C_];   // x pre-converted to tf32 bits
__device__ uint32_t gw1_tf[3*C_*C_];    // wqkv pre-converted
__device__ uint32_t gw2_tf[C_*C_];      // wproj pre-converted

// ---------------------------------------------------------------------------
// helpers
// ---------------------------------------------------------------------------
__device__ __forceinline__ uint32_t f2tf(float f) {
    uint32_t u;
    asm("cvt.rna.tf32.f32 %0, %1;" : "=r"(u) : "f"(f));
    return u;
}

__device__ __forceinline__ void mma8(float* c, const uint32_t* a, const uint32_t* b) {
    asm volatile(
        "mma.sync.aligned.m16n8k8.row.col.f32.tf32.tf32.f32 "
        "{%0,%1,%2,%3},{%4,%5,%6,%7},{%8,%9},{%0,%1,%2,%3};"
        : "+f"(c[0]), "+f"(c[1]), "+f"(c[2]), "+f"(c[3])
        : "r"(a[0]), "r"(a[1]), "r"(a[2]), "r"(a[3]), "r"(b[0]), "r"(b[1]));
}

__device__ __forceinline__ uint32_t smem_u32(const void* p) {
    uint32_t a;
    asm("{ .reg .u64 t; cvta.to.shared.u64 t, %1; cvt.u32.u64 %0, t; }"
        : "=r"(a) : "l"(p));
    return a;
}

__device__ __forceinline__ void ldsm4(uint32_t* r, uint32_t addr) {
    asm volatile("ldmatrix.sync.aligned.m8n8.x4.shared.b16 {%0,%1,%2,%3}, [%4];"
        : "=r"(r[0]), "=r"(r[1]), "=r"(r[2]), "=r"(r[3]) : "r"(addr));
}

__device__ __forceinline__ void cpasync16(uint32_t smem_addr, const void* gptr) {
    asm volatile("cp.async.cg.shared.global [%0], [%1], 16;"
        :: "r"(smem_addr), "l"(gptr) : "memory");
}
#define CP_COMMIT() asm volatile("cp.async.commit_group;" ::: "memory")

// ---------------------------------------------------------------------------
// Pre-convert pass: x, wqkv, wproj -> tf32 bit arrays
// ---------------------------------------------------------------------------
#define NXV ((B_*N_*C_)/4)
#define NW1V ((3*C_*C_)/4)
#define NW2V ((C_*C_)/4)
#define NTOTV (NXV + NW1V + NW2V)

__global__ __launch_bounds__(256)
void cvt_kernel(const float4* __restrict__ x, const float4* __restrict__ w1,
                const float4* __restrict__ w2)
{
    const int i = blockIdx.x * blockDim.x + threadIdx.x;
    if (i >= NTOTV) return;
    float4 v; uint4* dst;
    if (i < NXV)            { v = x[i];               dst = (uint4*)gx_tf  + i; }
    else if (i < NXV+NW1V)  { v = w1[i - NXV];        dst = (uint4*)gw1_tf + (i - NXV); }
    else                    { v = w2[i - NXV - NW1V]; dst = (uint4*)gw2_tf + (i - NXV - NW1V); }
    *dst = make_uint4(f2tf(v.x), f2tf(v.y), f2tf(v.z), f2tf(v.w));
}

// ---------------------------------------------------------------------------
// tf32 GEMM on pre-converted inputs (cp.async 3-stage, LDSM fragments).
// MODE 0: q,k scattered fp32; v scattered TRANSPOSED tf32 bits into g_vt.
// MODE 1: row-major fp32 store to Y.
// ---------------------------------------------------------------------------
#define KPG 36
#define STG_W (128*KPG)

template<int MODE>
__global__ __launch_bounds__(256)
void gemm_tf32(const uint32_t* __restrict__ A, const uint32_t* __restrict__ W,
               float* __restrict__ Y)
{
    extern __shared__ uint32_t smem[];
    uint32_t* As = smem;
    uint32_t* Ws = smem + 3*STG_W;

    const int tid  = threadIdx.x;
    const int warp = tid >> 5, lane = tid & 31;
    const int g    = lane >> 2, tig = lane & 3;
    const int wm   = (warp >> 2) * 64;
    const int wn   = (warp & 3)  * 32;
    const int bm   = blockIdx.y * 128;
    const int bn   = blockIdx.x * 128;
    const int K    = C_;
    const int nk   = K / 32;

    const int lrow = tid >> 1;
    const int lhf  = (tid & 1) * 16;
    const uint32_t sA0 = smem_u32(As) + (uint32_t)((lrow*KPG + lhf) * 4);
    const uint32_t sW0 = smem_u32(Ws) + (uint32_t)((lrow*KPG + lhf) * 4);
    const uint32_t* gA = A + (size_t)(bm + lrow) * K + lhf;
    const uint32_t* gW = W + (size_t)(bn + lrow) * K + lhf;

    const uint32_t a_lane = smem_u32(As)
        + (uint32_t)((((wm + (lane & 15)) * KPG + ((lane >> 4) << 2))) * 4);
    const uint32_t b_lane = smem_u32(Ws)
        + (uint32_t)((((wn + (lane & 7) + ((lane >> 4) << 3)) * KPG
                      + (((lane >> 3) & 1) << 2))) * 4);

    float acc[4][4][4];
    #pragma unroll
    for (int i = 0; i < 4; i++)
        #pragma unroll
        for (int j = 0; j < 4; j++)
            #pragma unroll
            for (int e = 0; e < 4; e++) acc[i][j][e] = 0.f;

    auto issue = [&](int s) {
        const uint32_t so = (uint32_t)((s % 3) * STG_W * 4);
        const uint32_t* ga = gA + s*32;
        const uint32_t* gw = gW + s*32;
        #pragma unroll
        for (int q = 0; q < 4; q++) {
            cpasync16(sA0 + so + q*16, ga + q*4);
            cpasync16(sW0 + so + q*16, gw + q*4);
        }
        CP_COMMIT();
    };

    issue(0);
    if (nk > 1) issue(1);

    for (int i = 0; i < nk; i++) {
        if (i + 1 < nk) asm volatile("cp.async.wait_group 1;" ::: "memory");
        else            asm volatile("cp.async.wait_group 0;" ::: "memory");
        __syncthreads();
        if (i + 2 < nk) issue(i + 2);

        const uint32_t ab = a_lane + (uint32_t)((i % 3) * STG_W * 4);
        const uint32_t bb = b_lane + (uint32_t)((i % 3) * STG_W * 4);
        #pragma unroll
        for (int kk = 0; kk < 4; kk++) {
            const uint32_t kko = kk * 32;
            uint32_t af[4][4];
            #pragma unroll
            for (int mf = 0; mf < 4; mf++)
                ldsm4(af[mf], ab + (uint32_t)(mf*16*KPG*4) + kko);
            uint32_t bf0[4], bf1[4];
            ldsm4(bf0, bb + kko);
            ldsm4(bf1, bb + (uint32_t)(16*KPG*4) + kko);
            #pragma unroll
            for (int mf = 0; mf < 4; mf++) {
                mma8(acc[mf][0], af[mf], &bf0[0]);
                mma8(acc[mf][1], af[mf], &bf0[2]);
                mma8(acc[mf][2], af[mf], &bf1[0]);
                mma8(acc[mf][3], af[mf], &bf1[2]);
            }
        }
    }

    // epilogue
    #pragma unroll
    for (int mf = 0; mf < 4; mf++) {
        #pragma unroll
        for (int rr = 0; rr < 2; rr++) {
            const int m = bm + wm + mf*16 + g + rr*8;
            const int b = m >> 10;
            const int n = m & 1023;
            #pragma unroll
            for (int nf = 0; nf < 4; nf++) {
                const int c = bn + wn + nf*8 + 2*tig;
                const float vx = acc[mf][nf][rr*2 + 0];
                const float vy = acc[mf][nf][rr*2 + 1];
                if (MODE == 1) {
                    float2 v2; v2.x = vx; v2.y = vy;
                    *(float2*)&Y[(size_t)m * C_ + c] = v2;
                } else {
                    const int s = c / C_;
                    const int w = c - s * C_;
                    const int h = w >> 6;
                    const int d = w & 63;
                    if (s == 0) {
                        float2 v2; v2.x = vx; v2.y = vy;
                        *(float2*)&g_q[((b*H_ + h)*N_ + n)*D_ + d] = v2;
                    } else if (s == 1) {
                        float2 v2; v2.x = vx; v2.y = vy;
                        *(float2*)&g_k[((b*H_ + h)*N_ + n)*D_ + d] = v2;
                    } else {
                        // transposed: g_vt[bh][d][n]
                        uint32_t* vt = g_vt + ((size_t)(b*H_ + h)*D_ + d)*N_ + n;
                        vt[0]  = f2tf(vx);
                        vt[N_] = f2tf(vy);   // d+1
                    }
                }
            }
        }
    }
}

// ---------------------------------------------------------------------------
// Per-head LayerNorm over D=64 (q also *SCALE). Reads fp32, WRITES TF32 BITS.
// ---------------------------------------------------------------------------
__global__ __launch_bounds__(256)
void ln_kernel()
{
    const int warp = (blockIdx.x * blockDim.x + threadIdx.x) >> 5;
    const int lane = threadIdx.x & 31;
    const int nrows = BH_ * N_;
    if (warp >= 2 * nrows) return;

    float* buf  = (warp < nrows) ? g_q : g_k;
    const float scale = (warp < nrows) ? 0.125f : 1.0f;
    const int row = (warp < nrows) ? warp : warp - nrows;

    float2 x = *(float2*)&buf[(size_t)row*64 + lane*2];
    float sum = x.x + x.y;
    #pragma unroll
    for (int o = 16; o > 0; o >>= 1) sum += __shfl_xor_sync(0xffffffffu, sum, o);
    const float mean = sum * (1.0f/64.0f);
    const float dx = x.x - mean, dy = x.y - mean;
    float vs = dx*dx + dy*dy;
    #pragma unroll
    for (int o = 16; o > 0; o >>= 1) vs += __shfl_xor_sync(0xffffffffu, vs, o);
    const float inv = rsqrtf(vs * (1.0f/64.0f) + 1e-5f) * scale;
    *(uint2*)&((uint32_t*)buf)[(size_t)row*64 + lane*2] =
        make_uint2(f2tf(dx * inv), f2tf(dy * inv));
}

// ---------------------------------------------------------------------------
// Flash attention v3: 128 threads, 64 q rows/block, cp.async double-buffered
// K and V^T tiles (pure bit copies), ONE __syncthreads per KV tile.
// Q frags hoisted in registers. P in smem (tf32 bits).
// ---------------------------------------------------------------------------
#define FPT 68
#define FTILE_W (64*FPT)   // 4352 words per tile buffer

__global__ __launch_bounds__(128)
void flash_tf32()
{
    extern __shared__ uint32_t fsm[];
    // layout: Ps [64][FPT] | K0 | V0 | K1 | V1  (each [64][FPT])
    uint32_t* Ps = fsm;

    const int bh    = blockIdx.y;
    const int qtile = blockIdx.x;       // 0..15 (64 rows each)
    const int b = bh / H_;
    const int h = bh - b * H_;

    const uint32_t* Qb  = (const uint32_t*)g_q + (size_t)bh * N_ * D_
                        + (size_t)qtile * 64 * D_;
    const uint32_t* Kb  = (const uint32_t*)g_k + (size_t)bh * N_ * D_;
    const uint32_t* Vtb = g_vt + (size_t)bh * D_ * N_;

    const int tid  = threadIdx.x;
    const int warp = tid >> 5, lane = tid & 31;
    const int g    = lane >> 2, tig = lane & 3;
    const int wband = warp * 16;

    const uint32_t smbase = smem_u32(fsm);
    const uint32_t bRowOff = (uint32_t)(((lane & 7) + ((lane >> 4) << 3)) * FPT
                                        + (((lane >> 3) & 1) << 2)) * 4;
    const uint32_t pa_lane = smbase
        + (uint32_t)(((wband + (lane & 15)) * FPT + ((lane >> 4) << 2)) * 4);

    // staging mapping: 8 chunks of 16B per thread per matrix
    const int srow = tid >> 4;          // base row group (reused with +8q below)

    // issue K+V^T tile j into stage s = j&1
    auto issue = [&](int j) {
        const int s = j & 1;
        const uint32_t kbase = smbase + (uint32_t)((1 + 2*s) * FTILE_W * 4);
        const uint32_t vbase = kbase + (uint32_t)(FTILE_W * 4);
        #pragma unroll
        for (int q = 0; q < 8; q++) {
            const int i = tid + 128*q;
            const int r = i >> 4, ch = (i & 15) << 2;
            cpasync16(kbase + (uint32_t)((r*FPT + ch) * 4),
                      Kb + (size_t)j*4096 + r*64 + ch);
            cpasync16(vbase + (uint32_t)((r*FPT + ch) * 4),
                      Vtb + (size_t)r*N_ + j*64 + ch);
        }
        CP_COMMIT();
    };

    issue(0);
    // stage Q bits into Ps
    #pragma unroll
    for (int q = 0; q < 8; q++) {
        const int i = tid + 128*q;
        const int r = i >> 4, ch = (i & 15) << 2;
        *(uint4*)&Ps[r*FPT + ch] = *(const uint4*)(Qb + r*64 + ch);
    }
    __syncthreads();

    // hoist Q frags (already tf32 bits)
    uint32_t qa[8][4];
    #pragma unroll
    for (int kf = 0; kf < 8; kf++)
        ldsm4(qa[kf], pa_lane + kf*32);

    float o[8][4];
    #pragma unroll
    for (int nf = 0; nf < 8; nf++)
        #pragma unroll
        for (int e = 0; e < 4; e++) o[nf][e] = 0.f;
    float m0 = -1e30f, m1 = -1e30f, l0 = 0.f, l1 = 0.f;

    for (int j = 0; j < 16; j++) {
        __syncthreads();    // all warps done reading stage (j-1)&1 (and Q hoisted, j=0)
        if (j + 1 < 16) {
            issue(j + 1);
            asm volatile("cp.async.wait_group 1;" ::: "memory");
        } else {
            asm volatile("cp.async.wait_group 0;" ::: "memory");
        }
        __syncthreads();    // stage j visible to all

        const int s = j & 1;
        const uint32_t kb_lane = smbase + (uint32_t)((1 + 2*s) * FTILE_W * 4) + bRowOff;
        const uint32_t vb_lane = kb_lane + (uint32_t)(FTILE_W * 4);

        // S = Q @ K^T   (warp: 16 rows x 64 cols)
        float sacc[8][4];
        #pragma unroll
        for (int nf = 0; nf < 8; nf++)
            #pragma unroll
            for (int e = 0; e < 4; e++) sacc[nf][e] = 0.f;

        #pragma unroll
        for (int kf = 0; kf < 8; kf++) {
            uint32_t bfr[4][4];
            #pragma unroll
            for (int nfp = 0; nfp < 4; nfp++)
                ldsm4(bfr[nfp], kb_lane + (uint32_t)((nfp*16*FPT + kf*8) * 4));
            #pragma unroll
            for (int nf = 0; nf < 8; nf++)
                mma8(sacc[nf], qa[kf], &bfr[nf >> 1][(nf & 1) * 2]);
        }

        // online softmax (rows r0 = wband+g, r1 = r0+8)
        float mx0 = -1e30f, mx1 = -1e30f;
        #pragma unroll
        for (int nf = 0; nf < 8; nf++) {
            mx0 = fmaxf(mx0, fmaxf(sacc[nf][0], sacc[nf][1]));
            mx1 = fmaxf(mx1, fmaxf(sacc[nf][2], sacc[nf][3]));
        }
        mx0 = fmaxf(mx0, __shfl_xor_sync(0xffffffffu, mx0, 1));
        mx0 = fmaxf(mx0, __shfl_xor_sync(0xffffffffu, mx0, 2));
        mx1 = fmaxf(mx1, __shfl_xor_sync(0xffffffffu, mx1, 1));
        mx1 = fmaxf(mx1, __shfl_xor_sync(0xffffffffu, mx1, 2));

        const float mn0 = fmaxf(m0, mx0);
        const float mn1 = fmaxf(m1, mx1);
        const float corr0 = __expf(m0 - mn0);
        const float corr1 = __expf(m1 - mn1);
        m0 = mn0; m1 = mn1;

        float rs0 = 0.f, rs1 = 0.f;
        #pragma unroll
        for (int nf = 0; nf < 8; nf++) {
            const float p0 = __expf(sacc[nf][0] - mn0);
            const float p1 = __expf(sacc[nf][1] - mn0);
            const float p2 = __expf(sacc[nf][2] - mn1);
            const float p3 = __expf(sacc[nf][3] - mn1);
            rs0 += p0 + p1;
            rs1 += p2 + p3;
            *(uint2*)&Ps[(wband + g    )*FPT + nf*8 + 2*tig] =
                make_uint2(f2tf(p0), f2tf(p1));
            *(uint2*)&Ps[(wband + g + 8)*FPT + nf*8 + 2*tig] =
                make_uint2(f2tf(p2), f2tf(p3));
        }
        rs0 += __shfl_xor_sync(0xffffffffu, rs0, 1);
        rs0 += __shfl_xor_sync(0xffffffffu, rs0, 2);
        rs1 += __shfl_xor_sync(0xffffffffu, rs1, 1);
        rs1 += __shfl_xor_sync(0xffffffffu, rs1, 2);
        l0 = l0 * corr0 + rs0;
        l1 = l1 * corr1 + rs1;

        #pragma unroll
        for (int nf = 0; nf < 8; nf++) {
            o[nf][0] *= corr0; o[nf][1] *= corr0;
            o[nf][2] *= corr1; o[nf][3] *= corr1;
        }
        __syncwarp();

        // O += P @ V
        #pragma unroll
        for (int kf = 0; kf < 8; kf++) {
            uint32_t pa[4];
            ldsm4(pa, pa_lane + kf*32);
            uint32_t bv[4][4];
            #pragma unroll
            for (int nfp = 0; nfp < 4; nfp++)
                ldsm4(bv[nfp], vb_lane + (uint32_t)((nfp*16*FPT + kf*8) * 4));
            #pragma unroll
            for (int nf = 0; nf < 8; nf++)
                mma8(o[nf], pa, &bv[nf >> 1][(nf & 1) * 2]);
        }
        __syncwarp();
    }

    // epilogue: O / l -> g_ao as tf32 bits
    const float inv0 = 1.0f / l0;
    const float inv1 = 1.0f / l1;
    const int n0 = qtile*64 + wband + g;
    const int n1 = n0 + 8;
    #pragma unroll
    for (int nf = 0; nf < 8; nf++) {
        const int d = h*64 + nf*8 + 2*tig;
        *(uint2*)&g_ao[((size_t)b*N_ + n0)*C_ + d] =
            make_uint2(f2tf(o[nf][0]*inv0), f2tf(o[nf][1]*inv0));
        *(uint2*)&g_ao[((size_t)b*N_ + n1)*C_ + d] =
            make_uint2(f2tf(o[nf][2]*inv1), f2tf(o[nf][3]*inv1));
    }
}

// ---------------------------------------------------------------------------
extern "C" void kernel_launch(void* const* d_in, const int* in_sizes, int n_in,
                              void* d_out, int out_size)
{
    const float* x     = (const float*)d_in[0];   // [B,N,C]
    const float* wqkv  = (const float*)d_in[1];   // [3C,C]
    const float* wproj = (const float*)d_in[2];   // [C,C]
    float* out = (float*)d_out;                   // [B,N,C]

    uint32_t* d_gx;  cudaGetSymbolAddress((void**)&d_gx,  gx_tf);
    uint32_t* d_gw1; cudaGetSymbolAddress((void**)&d_gw1, gw1_tf);
    uint32_t* d_gw2; cudaGetSymbolAddress((void**)&d_gw2, gw2_tf);
    uint32_t* d_gao; cudaGetSymbolAddress((void**)&d_gao, g_ao);

    const int gsmem = 6 * STG_W * (int)sizeof(uint32_t);   // 110592

    // 0) pre-convert x, wqkv, wproj to tf32 bits
    {
        const int blocks = (NTOTV + 255) / 256;
        cvt_kernel<<<blocks, 256>>>((const float4*)x, (const float4*)wqkv,
                                    (const float4*)wproj);
    }

    // 1) QKV GEMM -> q/k fp32, v transposed tf32 bits (g_vt)
    {
        cudaFuncSetAttribute(gemm_tf32<0>,
                             cudaFuncAttributeMaxDynamicSharedMemorySize, gsmem);
        dim3 grid(3*C_/128, (B_*N_)/128);   // (18, 64)
        gemm_tf32<0><<<grid, 256, gsmem>>>(d_gx, d_gw1, nullptr);
    }

    // 2) LayerNorm on q (*SCALE) and k -> tf32 bits in place
    {
        const int warps = 2 * BH_ * N_;
        const int blocks = (warps * 32 + 255) / 256;
        ln_kernel<<<blocks, 256>>>();
    }

    // 3) Flash attention -> g_ao (tf32 bits)
    {
        const int fsmem = 5 * FTILE_W * (int)sizeof(uint32_t);   // 87040
        cudaFuncSetAttribute(flash_tf32,
                             cudaFuncAttributeMaxDynamicSharedMemorySize, fsmem);
        dim3 grid(N_/64, BH_);   // (16, 96)
        flash_tf32<<<grid, 128, fsmem>>>();
    }

    // 4) Output projection (A = g_ao tf32 bits)
    {
        cudaFuncSetAttribute(gemm_tf32<1>,
                             cudaFuncAttributeMaxDynamicSharedMemorySize, gsmem);
        dim3 grid(C_/128, (B_*N_)/128);     // (6, 64)
        gemm_tf32<1><<<grid, 256, gsmem>>>(d_gao, d_gw2, out);
    }
}

// round 14
// speedup vs baseline: 1.1622x; 1.0547x over previous
#include <cuda_runtime.h>
#include <math.h>
#include <stdint.h>

#define B_ 8
#define N_ 1024
#define C_ 768
#define H_ 12
#define D_ 64
#define BH_ (B_*H_)

// Scratch (device globals — no allocation allowed)
__device__ float    g_q [BH_*N_*D_];    // fp32 from GEMM; LN rewrites tf32 bits
__device__ float    g_k [BH_*N_*D_];    // fp32 from GEMM; LN rewrites tf32 bits
__device__ uint32_t g_vt[BH_*D_*N_];    // V^T tf32 bits: [bh][d][n]
__device__ uint32_t g_ao[B_*N_*C_];     // attention output, tf32 bits, [B,N,C]
__device__ uint32_t gx_tf [B_*N_*C_];   // x pre-converted to tf32 bits
__device__ uint32_t gw1_tf[3*C_*C_];    // wqkv pre-converted
__device__ uint32_t gw2_tf[C_*C_];      // wproj pre-converted

// ---------------------------------------------------------------------------
// helpers
// ---------------------------------------------------------------------------
__device__ __forceinline__ uint32_t f2tf(float f) {
    uint32_t u;
    asm("cvt.rna.tf32.f32 %0, %1;" : "=r"(u) : "f"(f));
    return u;
}

__device__ __forceinline__ void mma8(float* c, const uint32_t* a, const uint32_t* b) {
    asm volatile(
        "mma.sync.aligned.m16n8k8.row.col.f32.tf32.tf32.f32 "
        "{%0,%1,%2,%3},{%4,%5,%6,%7},{%8,%9},{%0,%1,%2,%3};"
        : "+f"(c[0]), "+f"(c[1]), "+f"(c[2]), "+f"(c[3])
        : "r"(a[0]), "r"(a[1]), "r"(a[2]), "r"(a[3]), "r"(b[0]), "r"(b[1]));
}

__device__ __forceinline__ uint32_t smem_u32(const void* p) {
    uint32_t a;
    asm("{ .reg .u64 t; cvta.to.shared.u64 t, %1; cvt.u32.u64 %0, t; }"
        : "=r"(a) : "l"(p));
    return a;
}

__device__ __forceinline__ void ldsm4(uint32_t* r, uint32_t addr) {
    asm volatile("ldmatrix.sync.aligned.m8n8.x4.shared.b16 {%0,%1,%2,%3}, [%4];"
        : "=r"(r[0]), "=r"(r[1]), "=r"(r[2]), "=r"(r[3]) : "r"(addr));
}

__device__ __forceinline__ void cpasync16(uint32_t smem_addr, const void* gptr) {
    asm volatile("cp.async.cg.shared.global [%0], [%1], 16;"
        :: "r"(smem_addr), "l"(gptr) : "memory");
}
#define CP_COMMIT() asm volatile("cp.async.commit_group;" ::: "memory")

// ---------------------------------------------------------------------------
// Pre-convert pass: x, wqkv, wproj -> tf32 bit arrays
// ---------------------------------------------------------------------------
#define NXV ((B_*N_*C_)/4)
#define NW1V ((3*C_*C_)/4)
#define NW2V ((C_*C_)/4)
#define NTOTV (NXV + NW1V + NW2V)

__global__ __launch_bounds__(256)
void cvt_kernel(const float4* __restrict__ x, const float4* __restrict__ w1,
                const float4* __restrict__ w2)
{
    const int i = blockIdx.x * blockDim.x + threadIdx.x;
    if (i >= NTOTV) return;
    float4 v; uint4* dst;
    if (i < NXV)            { v = x[i];               dst = (uint4*)gx_tf  + i; }
    else if (i < NXV+NW1V)  { v = w1[i - NXV];        dst = (uint4*)gw1_tf + (i - NXV); }
    else                    { v = w2[i - NXV - NW1V]; dst = (uint4*)gw2_tf + (i - NXV - NW1V); }
    *dst = make_uint4(f2tf(v.x), f2tf(v.y), f2tf(v.z), f2tf(v.w));
}

// ---------------------------------------------------------------------------
// tf32 GEMM on pre-converted inputs (cp.async 3-stage, LDSM fragments).
// MODE 0: q,k scattered fp32; v scattered TRANSPOSED tf32 bits into g_vt.
// MODE 1: row-major fp32 store to Y.
// ---------------------------------------------------------------------------
#define KPG 36
#define STG_W (128*KPG)

template<int MODE>
__global__ __launch_bounds__(256)
void gemm_tf32(const uint32_t* __restrict__ A, const uint32_t* __restrict__ W,
               float* __restrict__ Y)
{
    extern __shared__ uint32_t smem[];
    uint32_t* As = smem;
    uint32_t* Ws = smem + 3*STG_W;

    const int tid  = threadIdx.x;
    const int warp = tid >> 5, lane = tid & 31;
    const int g    = lane >> 2, tig = lane & 3;
    const int wm   = (warp >> 2) * 64;
    const int wn   = (warp & 3)  * 32;
    const int bm   = blockIdx.y * 128;
    const int bn   = blockIdx.x * 128;
    const int K    = C_;
    const int nk   = K / 32;

    const int lrow = tid >> 1;
    const int lhf  = (tid & 1) * 16;
    const uint32_t sA0 = smem_u32(As) + (uint32_t)((lrow*KPG + lhf) * 4);
    const uint32_t sW0 = smem_u32(Ws) + (uint32_t)((lrow*KPG + lhf) * 4);
    const uint32_t* gA = A + (size_t)(bm + lrow) * K + lhf;
    const uint32_t* gW = W + (size_t)(bn + lrow) * K + lhf;

    const uint32_t a_lane = smem_u32(As)
        + (uint32_t)((((wm + (lane & 15)) * KPG + ((lane >> 4) << 2))) * 4);
    const uint32_t b_lane = smem_u32(Ws)
        + (uint32_t)((((wn + (lane & 7) + ((lane >> 4) << 3)) * KPG
                      + (((lane >> 3) & 1) << 2))) * 4);

    float acc[4][4][4];
    #pragma unroll
    for (int i = 0; i < 4; i++)
        #pragma unroll
        for (int j = 0; j < 4; j++)
            #pragma unroll
            for (int e = 0; e < 4; e++) acc[i][j][e] = 0.f;

    auto issue = [&](int s) {
        const uint32_t so = (uint32_t)((s % 3) * STG_W * 4);
        const uint32_t* ga = gA + s*32;
        const uint32_t* gw = gW + s*32;
        #pragma unroll
        for (int q = 0; q < 4; q++) {
            cpasync16(sA0 + so + q*16, ga + q*4);
            cpasync16(sW0 + so + q*16, gw + q*4);
        }
        CP_COMMIT();
    };

    issue(0);
    if (nk > 1) issue(1);

    for (int i = 0; i < nk; i++) {
        if (i + 1 < nk) asm volatile("cp.async.wait_group 1;" ::: "memory");
        else            asm volatile("cp.async.wait_group 0;" ::: "memory");
        __syncthreads();
        if (i + 2 < nk) issue(i + 2);

        const uint32_t ab = a_lane + (uint32_t)((i % 3) * STG_W * 4);
        const uint32_t bb = b_lane + (uint32_t)((i % 3) * STG_W * 4);
        #pragma unroll
        for (int kk = 0; kk < 4; kk++) {
            const uint32_t kko = kk * 32;
            uint32_t af[4][4];
            #pragma unroll
            for (int mf = 0; mf < 4; mf++)
                ldsm4(af[mf], ab + (uint32_t)(mf*16*KPG*4) + kko);
            uint32_t bf0[4], bf1[4];
            ldsm4(bf0, bb + kko);
            ldsm4(bf1, bb + (uint32_t)(16*KPG*4) + kko);
            #pragma unroll
            for (int mf = 0; mf < 4; mf++) {
                mma8(acc[mf][0], af[mf], &bf0[0]);
                mma8(acc[mf][1], af[mf], &bf0[2]);
                mma8(acc[mf][2], af[mf], &bf1[0]);
                mma8(acc[mf][3], af[mf], &bf1[2]);
            }
        }
    }

    // epilogue
    #pragma unroll
    for (int mf = 0; mf < 4; mf++) {
        #pragma unroll
        for (int rr = 0; rr < 2; rr++) {
            const int m = bm + wm + mf*16 + g + rr*8;
            const int b = m >> 10;
            const int n = m & 1023;
            #pragma unroll
            for (int nf = 0; nf < 4; nf++) {
                const int c = bn + wn + nf*8 + 2*tig;
                const float vx = acc[mf][nf][rr*2 + 0];
                const float vy = acc[mf][nf][rr*2 + 1];
                if (MODE == 1) {
                    float2 v2; v2.x = vx; v2.y = vy;
                    *(float2*)&Y[(size_t)m * C_ + c] = v2;
                } else {
                    const int s = c / C_;
                    const int w = c - s * C_;
                    const int h = w >> 6;
                    const int d = w & 63;
                    if (s == 0) {
                        float2 v2; v2.x = vx; v2.y = vy;
                        *(float2*)&g_q[((b*H_ + h)*N_ + n)*D_ + d] = v2;
                    } else if (s == 1) {
                        float2 v2; v2.x = vx; v2.y = vy;
                        *(float2*)&g_k[((b*H_ + h)*N_ + n)*D_ + d] = v2;
                    } else {
                        uint32_t* vt = g_vt + ((size_t)(b*H_ + h)*D_ + d)*N_ + n;
                        vt[0]  = f2tf(vx);
                        vt[N_] = f2tf(vy);   // d+1
                    }
                }
            }
        }
    }
}

// ---------------------------------------------------------------------------
// Per-head LayerNorm over D=64 (q also *SCALE). Reads fp32, WRITES TF32 BITS.
// ---------------------------------------------------------------------------
__global__ __launch_bounds__(256)
void ln_kernel()
{
    const int warp = (blockIdx.x * blockDim.x + threadIdx.x) >> 5;
    const int lane = threadIdx.x & 31;
    const int nrows = BH_ * N_;
    if (warp >= 2 * nrows) return;

    float* buf  = (warp < nrows) ? g_q : g_k;
    const float scale = (warp < nrows) ? 0.125f : 1.0f;
    const int row = (warp < nrows) ? warp : warp - nrows;

    float2 x = *(float2*)&buf[(size_t)row*64 + lane*2];
    float sum = x.x + x.y;
    #pragma unroll
    for (int o = 16; o > 0; o >>= 1) sum += __shfl_xor_sync(0xffffffffu, sum, o);
    const float mean = sum * (1.0f/64.0f);
    const float dx = x.x - mean, dy = x.y - mean;
    float vs = dx*dx + dy*dy;
    #pragma unroll
    for (int o = 16; o > 0; o >>= 1) vs += __shfl_xor_sync(0xffffffffu, vs, o);
    const float inv = rsqrtf(vs * (1.0f/64.0f) + 1e-5f) * scale;
    *(uint2*)&((uint32_t*)buf)[(size_t)row*64 + lane*2] =
        make_uint2(f2tf(dx * inv), f2tf(dy * inv));
}

// ---------------------------------------------------------------------------
// Flash attention v4: 256 threads, 128 q rows/block, cp.async double-buffered
// K/V^T tiles, ONE wait+2 barriers per tile, Q frags hoisted in registers.
// Smem: Ps[128][FPT] (Q staging then P bits) | K0 | V0 | K1 | V1 ([64][FPT]).
// ---------------------------------------------------------------------------
#define FPT 68
#define FTILE_W (64*FPT)    // 4352 words per tile buffer
#define PS_W (128*FPT)      // 8704 words

__global__ __launch_bounds__(256, 2)
void flash_tf32()
{
    extern __shared__ uint32_t fsm[];
    uint32_t* Ps = fsm;

    const int bh    = blockIdx.y;
    const int qtile = blockIdx.x;       // 0..7 (128 rows each)
    const int b = bh / H_;
    const int h = bh - b * H_;

    const uint32_t* Qb  = (const uint32_t*)g_q + (size_t)bh * N_ * D_
                        + (size_t)qtile * 128 * D_;
    const uint32_t* Kb  = (const uint32_t*)g_k + (size_t)bh * N_ * D_;
    const uint32_t* Vtb = g_vt + (size_t)bh * D_ * N_;

    const int tid  = threadIdx.x;
    const int warp = tid >> 5, lane = tid & 31;
    const int g    = lane >> 2, tig = lane & 3;
    const int wband = warp * 16;        // q rows [wband, wband+16)

    const uint32_t smbase = smem_u32(fsm);
    const uint32_t bRowOff = (uint32_t)(((lane & 7) + ((lane >> 4) << 3)) * FPT
                                        + (((lane >> 3) & 1) << 2)) * 4;
    const uint32_t pa_lane = smbase
        + (uint32_t)(((wband + (lane & 15)) * FPT + ((lane >> 4) << 2)) * 4);

    // issue K+V^T tile j into stage s = j&1 (pure bit copies)
    auto issue = [&](int j) {
        const int s = j & 1;
        const uint32_t kbase = smbase + (uint32_t)((PS_W + 2*s*FTILE_W) * 4);
        const uint32_t vbase = kbase + (uint32_t)(FTILE_W * 4);
        #pragma unroll
        for (int q = 0; q < 4; q++) {
            const int i = tid + 256*q;
            const int r = i >> 4, ch = (i & 15) << 2;
            cpasync16(kbase + (uint32_t)((r*FPT + ch) * 4),
                      Kb + (size_t)j*4096 + r*64 + ch);
            cpasync16(vbase + (uint32_t)((r*FPT + ch) * 4),
                      Vtb + (size_t)r*N_ + j*64 + ch);
        }
        CP_COMMIT();
    };

    issue(0);
    // stage Q bits into Ps (128 rows)
    #pragma unroll
    for (int q = 0; q < 8; q++) {
        const int i = tid + 256*q;
        const int r = i >> 4, ch = (i & 15) << 2;
        *(uint4*)&Ps[r*FPT + ch] = *(const uint4*)(Qb + r*64 + ch);
    }
    __syncthreads();

    // hoist Q frags (already tf32 bits)
    uint32_t qa[8][4];
    #pragma unroll
    for (int kf = 0; kf < 8; kf++)
        ldsm4(qa[kf], pa_lane + kf*32);

    float o[8][4];
    #pragma unroll
    for (int nf = 0; nf < 8; nf++)
        #pragma unroll
        for (int e = 0; e < 4; e++) o[nf][e] = 0.f;
    float m0 = -1e30f, m1 = -1e30f, l0 = 0.f, l1 = 0.f;

    for (int j = 0; j < 16; j++) {
        __syncthreads();    // all warps done reading stage (j+1)&1 / Q hoisted
        if (j + 1 < 16) {
            issue(j + 1);
            asm volatile("cp.async.wait_group 1;" ::: "memory");
        } else {
            asm volatile("cp.async.wait_group 0;" ::: "memory");
        }
        __syncthreads();    // stage j visible to all

        const int s = j & 1;
        const uint32_t kb_lane = smbase + (uint32_t)((PS_W + 2*s*FTILE_W) * 4) + bRowOff;
        const uint32_t vb_lane = kb_lane + (uint32_t)(FTILE_W * 4);

        // S = Q @ K^T   (warp: 16 rows x 64 cols)
        float sacc[8][4];
        #pragma unroll
        for (int nf = 0; nf < 8; nf++)
            #pragma unroll
            for (int e = 0; e < 4; e++) sacc[nf][e] = 0.f;

        #pragma unroll
        for (int kf = 0; kf < 8; kf++) {
            uint32_t bfr[4][4];
            #pragma unroll
            for (int nfp = 0; nfp < 4; nfp++)
                ldsm4(bfr[nfp], kb_lane + (uint32_t)((nfp*16*FPT + kf*8) * 4));
            #pragma unroll
            for (int nf = 0; nf < 8; nf++)
                mma8(sacc[nf], qa[kf], &bfr[nf >> 1][(nf & 1) * 2]);
        }

        // online softmax (rows r0 = wband+g, r1 = r0+8)
        float mx0 = -1e30f, mx1 = -1e30f;
        #pragma unroll
        for (int nf = 0; nf < 8; nf++) {
            mx0 = fmaxf(mx0, fmaxf(sacc[nf][0], sacc[nf][1]));
            mx1 = fmaxf(mx1, fmaxf(sacc[nf][2], sacc[nf][3]));
        }
        mx0 = fmaxf(mx0, __shfl_xor_sync(0xffffffffu, mx0, 1));
        mx0 = fmaxf(mx0, __shfl_xor_sync(0xffffffffu, mx0, 2));
        mx1 = fmaxf(mx1, __shfl_xor_sync(0xffffffffu, mx1, 1));
        mx1 = fmaxf(mx1, __shfl_xor_sync(0xffffffffu, mx1, 2));

        const float mn0 = fmaxf(m0, mx0);
        const float mn1 = fmaxf(m1, mx1);
        const float corr0 = __expf(m0 - mn0);
        const float corr1 = __expf(m1 - mn1);
        m0 = mn0; m1 = mn1;

        float rs0 = 0.f, rs1 = 0.f;
        #pragma unroll
        for (int nf = 0; nf < 8; nf++) {
            const float p0 = __expf(sacc[nf][0] - mn0);
            const float p1 = __expf(sacc[nf][1] - mn0);
            const float p2 = __expf(sacc[nf][2] - mn1);
            const float p3 = __expf(sacc[nf][3] - mn1);
            rs0 += p0 + p1;
            rs1 += p2 + p3;
            *(uint2*)&Ps[(wband + g    )*FPT + nf*8 + 2*tig] =
                make_uint2(f2tf(p0), f2tf(p1));
            *(uint2*)&Ps[(wband + g + 8)*FPT + nf*8 + 2*tig] =
                make_uint2(f2tf(p2), f2tf(p3));
        }
        rs0 += __shfl_xor_sync(0xffffffffu, rs0, 1);
        rs0 += __shfl_xor_sync(0xffffffffu, rs0, 2);
        rs1 += __shfl_xor_sync(0xffffffffu, rs1, 1);
        rs1 += __shfl_xor_sync(0xffffffffu, rs1, 2);
        l0 = l0 * corr0 + rs0;
        l1 = l1 * corr1 + rs1;

        #pragma unroll
        for (int nf = 0; nf < 8; nf++) {
            o[nf][0] *= corr0; o[nf][1] *= corr0;
            o[nf][2] *= corr1; o[nf][3] *= corr1;
        }
        __syncwarp();

        // O += P @ V
        #pragma unroll
        for (int kf = 0; kf < 8; kf++) {
            uint32_t pa[4];
            ldsm4(pa, pa_lane + kf*32);
            uint32_t bv[4][4];
            #pragma unroll
            for (int nfp = 0; nfp < 4; nfp++)
                ldsm4(bv[nfp], vb_lane + (uint32_t)((nfp*16*FPT + kf*8) * 4));
            #pragma unroll
            for (int nf = 0; nf < 8; nf++)
                mma8(o[nf], pa, &bv[nf >> 1][(nf & 1) * 2]);
        }
        __syncwarp();
    }

    // epilogue: O / l -> g_ao as tf32 bits
    const float inv0 = 1.0f / l0;
    const float inv1 = 1.0f / l1;
    const int n0 = qtile*128 + wband + g;
    const int n1 = n0 + 8;
    #pragma unroll
    for (int nf = 0; nf < 8; nf++) {
        const int d = h*64 + nf*8 + 2*tig;
        *(uint2*)&g_ao[((size_t)b*N_ + n0)*C_ + d] =
            make_uint2(f2tf(o[nf][0]*inv0), f2tf(o[nf][1]*inv0));
        *(uint2*)&g_ao[((size_t)b*N_ + n1)*C_ + d] =
            make_uint2(f2tf(o[nf][2]*inv1), f2tf(o[nf][3]*inv1));
    }
}

// ---------------------------------------------------------------------------
extern "C" void kernel_launch(void* const* d_in, const int* in_sizes, int n_in,
                              void* d_out, int out_size)
{
    const float* x     = (const float*)d_in[0];   // [B,N,C]
    const float* wqkv  = (const float*)d_in[1];   // [3C,C]
    const float* wproj = (const float*)d_in[2];   // [C,C]
    float* out = (float*)d_out;                   // [B,N,C]

    uint32_t* d_gx;  cudaGetSymbolAddress((void**)&d_gx,  gx_tf);
    uint32_t* d_gw1; cudaGetSymbolAddress((void**)&d_gw1, gw1_tf);
    uint32_t* d_gw2; cudaGetSymbolAddress((void**)&d_gw2, gw2_tf);
    uint32_t* d_gao; cudaGetSymbolAddress((void**)&d_gao, g_ao);

    const int gsmem = 6 * STG_W * (int)sizeof(uint32_t);   // 110592

    // 0) pre-convert x, wqkv, wproj to tf32 bits
    {
        const int blocks = (NTOTV + 255) / 256;
        cvt_kernel<<<blocks, 256>>>((const float4*)x, (const float4*)wqkv,
                                    (const float4*)wproj);
    }

    // 1) QKV GEMM -> q/k fp32, v transposed tf32 bits (g_vt)
    {
        cudaFuncSetAttribute(gemm_tf32<0>,
                             cudaFuncAttributeMaxDynamicSharedMemorySize, gsmem);
        dim3 grid(3*C_/128, (B_*N_)/128);   // (18, 64)
        gemm_tf32<0><<<grid, 256, gsmem>>>(d_gx, d_gw1, nullptr);
    }

    // 2) LayerNorm on q (*SCALE) and k -> tf32 bits in place
    {
        const int warps = 2 * BH_ * N_;
        const int blocks = (warps * 32 + 255) / 256;
        ln_kernel<<<blocks, 256>>>();
    }

    // 3) Flash attention -> g_ao (tf32 bits)
    {
        const int fsmem = (PS_W + 4*FTILE_W) * (int)sizeof(uint32_t);   // 104448
        cudaFuncSetAttribute(flash_tf32,
                             cudaFuncAttributeMaxDynamicSharedMemorySize, fsmem);
        dim3 grid(N_/128, BH_);   // (8, 96)
        flash_tf32<<<grid, 256, fsmem>>>();
    }

    // 4) Output projection (A = g_ao tf32 bits)
    {
        cudaFuncSetAttribute(gemm_tf32<1>,
                             cudaFuncAttributeMaxDynamicSharedMemorySize, gsmem);
        dim3 grid(C_/128, (B_*N_)/128);     // (6, 64)
        gemm_tf32<1><<<grid, 256, gsmem>>>(d_gao, d_gw2, out);
    }
}